// round 8
// baseline (speedup 1.0000x reference)
#include <cuda_runtime.h>
#include <cstdint>
#include <math.h>

#define BATCH  4
#define SEQ    2048
#define DMODEL 512
#define HEADS  8
#define HDIM   64

// tf32-rounded fp32 scratch (allocation-free rule: __device__ globals)
__device__ float g_q[BATCH * SEQ * DMODEL];
__device__ float g_k[BATCH * SEQ * HDIM];
__device__ float g_v[BATCH * SEQ * DMODEL];

// ---------------------------------------------------------------------------
// helpers (baseline PTX only — plain sm_103 target)
// ---------------------------------------------------------------------------
__device__ __forceinline__ uint32_t f2tf(float f) {
    uint32_t u;
    asm("cvt.rna.tf32.f32 %0, %1;" : "=r"(u) : "f"(f));
    return u;
}
__device__ __forceinline__ float ex2f(float x) {
    float r;
    asm("ex2.approx.f32 %0, %1;" : "=f"(r) : "f"(x));
    return r;
}
__device__ __forceinline__ void mma_tf32(float c[4], const uint32_t a[4],
                                         uint32_t b0, uint32_t b1) {
    asm volatile(
        "mma.sync.aligned.m16n8k8.row.col.f32.tf32.tf32.f32 "
        "{%0,%1,%2,%3}, {%4,%5,%6,%7}, {%8,%9}, {%0,%1,%2,%3};"
        : "+f"(c[0]), "+f"(c[1]), "+f"(c[2]), "+f"(c[3])
        : "r"(a[0]), "r"(a[1]), "r"(a[2]), "r"(a[3]), "r"(b0), "r"(b1));
}

// ---------------------------------------------------------------------------
// Fused QKV GEMM: 128-row CTA tile, BK=32, 256 threads.
// Warp tile 32x64 (4 warps in M x 2 in N): A-frags reused over 8 n-blocks,
// B-frags over 2 m-blocks -> 0.75 LDS.64 per MMA.
// grid = (9, 64): bx 0-3 Q slabs, 4-7 V slabs, 8 K.
// ---------------------------------------------------------------------------
#define APAD 40
#define WSTR 264

template <int NJW>   // n-blocks per warp: 8 (Q/V 128-wide), 4 (K 64-wide)
__device__ __forceinline__ void gemm_tile(
    const float* __restrict__ A, const float* __restrict__ W,
    const float* __restrict__ bias, float* __restrict__ C,
    int N, int n0, uint32_t* As, uint32_t* Wp)
{
    const int t    = threadIdx.x;
    const int w    = t >> 5;
    const int lane = t & 31;
    const int g    = lane >> 2;
    const int tg   = lane & 3;
    const int m0   = blockIdx.y * 128;
    const int wm   = w & 3;           // M quarter (32 rows)
    const int wn   = w >> 2;          // N half
    const int rowb = wm * 32;
    const int colb = wn * NJW * 8;

    const int arow = t >> 2, asg = t & 3;          // A loader task
    constexpr int WIT = (NJW == 8) ? 2 : 1;        // W loader iters
    const int wcq = t & (4 * NJW - 1);             // W col-quad

    float acc[2][NJW][4];
#pragma unroll
    for (int mb = 0; mb < 2; mb++)
#pragma unroll
        for (int j = 0; j < NJW; j++)
#pragma unroll
            for (int i = 0; i < 4; i++) acc[mb][j][i] = 0.f;

    float4 afr[2][2];
    float4 wfr[WIT][2];

    auto loadA = [&](int k0) {
#pragma unroll
        for (int i = 0; i < 2; i++) {
            const float* src = A + (size_t)(m0 + arow + 64 * i) * DMODEL + k0 + asg * 8;
            afr[i][0] = *(const float4*)src;
            afr[i][1] = *(const float4*)(src + 4);
        }
    };
    auto loadW = [&](int k0) {
#pragma unroll
        for (int i = 0; i < WIT; i++) {
            const int p  = (NJW == 8) ? ((t >> 5) + 8 * i) : (t >> 4);
            const int r0 = 8 * (p >> 2) + (p & 3);
            const float* src = W + (size_t)(k0 + r0) * N + n0 + 4 * wcq;
            wfr[i][0] = *(const float4*)src;
            wfr[i][1] = *(const float4*)(src + 4 * N);   // row r0+4
        }
    };
    auto storeA = [&]() {
#pragma unroll
        for (int i = 0; i < 2; i++) {
            uint32_t* d = As + (arow + 64 * i) * APAD + asg * 8;
            float4 u0 = afr[i][0], u1 = afr[i][1];
            *(uint4*)d       = make_uint4(f2tf(u0.x), f2tf(u1.x), f2tf(u0.y), f2tf(u1.y));
            *(uint4*)(d + 4) = make_uint4(f2tf(u0.z), f2tf(u1.z), f2tf(u0.w), f2tf(u1.w));
        }
    };
    auto storeW = [&]() {
#pragma unroll
        for (int i = 0; i < WIT; i++) {
            const int p = (NJW == 8) ? ((t >> 5) + 8 * i) : (t >> 4);
            uint32_t* d = Wp + p * WSTR + 8 * wcq;
            float4 w0 = wfr[i][0], w1 = wfr[i][1];
            *(uint4*)d       = make_uint4(f2tf(w0.x), f2tf(w1.x), f2tf(w0.y), f2tf(w1.y));
            *(uint4*)(d + 4) = make_uint4(f2tf(w0.z), f2tf(w1.z), f2tf(w0.w), f2tf(w1.w));
        }
    };

    loadA(0);
    loadW(0);

    for (int k0 = 0; k0 < DMODEL; k0 += 32) {
        storeA();
        storeW();
        __syncthreads();
        if (k0 + 32 < DMODEL) {
            loadA(k0 + 32);
            loadW(k0 + 32);
        }
#pragma unroll
        for (int s = 0; s < 4; s++) {
            uint32_t a[2][4];
#pragma unroll
            for (int mb = 0; mb < 2; mb++) {
                uint2 aLo = *(const uint2*)&As[(rowb + mb * 16 + g)     * APAD + 8 * s + 2 * tg];
                uint2 aHi = *(const uint2*)&As[(rowb + mb * 16 + g + 8) * APAD + 8 * s + 2 * tg];
                a[mb][0] = aLo.x; a[mb][1] = aHi.x; a[mb][2] = aLo.y; a[mb][3] = aHi.y;
            }
            const uint32_t* wrow = Wp + (s * 4 + tg) * WSTR;
#pragma unroll
            for (int j = 0; j < NJW; j++) {
                uint2 bp = *(const uint2*)&wrow[2 * (colb + j * 8 + g)];
                mma_tf32(acc[0][j], a[0], bp.x, bp.y);
                mma_tf32(acc[1][j], a[1], bp.x, bp.y);
            }
        }
        __syncthreads();
    }

#pragma unroll
    for (int mb = 0; mb < 2; mb++)
#pragma unroll
        for (int j = 0; j < NJW; j++) {
            const int col = n0 + colb + j * 8 + 2 * tg;
            const float b0v = bias ? bias[col] : 0.f;
            const float b1v = bias ? bias[col + 1] : 0.f;
            const int r0 = m0 + rowb + mb * 16 + g;
            float2 lo, hi;
            lo.x = __uint_as_float(f2tf(acc[mb][j][0] + b0v));
            lo.y = __uint_as_float(f2tf(acc[mb][j][1] + b1v));
            hi.x = __uint_as_float(f2tf(acc[mb][j][2] + b0v));
            hi.y = __uint_as_float(f2tf(acc[mb][j][3] + b1v));
            *(float2*)&C[(size_t)r0 * N + col]       = lo;
            *(float2*)&C[(size_t)(r0 + 8) * N + col] = hi;
        }
}

__global__ __launch_bounds__(256, 2)
void gemm_qkv(const float* __restrict__ A,
              const float* __restrict__ Wq, const float* __restrict__ bq,
              const float* __restrict__ Wk,
              const float* __restrict__ Wv, const float* __restrict__ bv,
              float* __restrict__ Cq, float* __restrict__ Ck, float* __restrict__ Cv)
{
    __shared__ uint32_t As[128 * APAD];
    __shared__ uint32_t Wp[16 * WSTR];

    const int bx = blockIdx.x;
    if (bx < 4)
        gemm_tile<8>(A, Wq, bq, Cq, DMODEL, bx * 128, As, Wp);
    else if (bx < 8)
        gemm_tile<8>(A, Wv, bv, Cv, DMODEL, (bx - 4) * 128, As, Wp);
    else
        gemm_tile<4>(A, Wk, nullptr, Ck, HDIM, 0, As, Wp);
}

// ---------------------------------------------------------------------------
// tf32 flash attention (Round-6 proven config). CTA = (x, h, b) handles
// q-tiles {x, 15-x}: uniform 17 k-tile iters -> 256 CTAs, one balanced wave.
// K pair-permuted (d,d+4), V row-pair interleaved -> all B loads LDS.64.
// 4 independent S-MMA chains. exp via ex2 with folded scale. P fed to MMA
// as raw fp32 (HW truncates to tf32). No online rescale (bounded logits).
// NOTE: bf16 anywhere in the PV product fails the 1e-3 gate (error does not
// average out — output is itself an average). tf32 is the minimum.
// ---------------------------------------------------------------------------
#define KTILE 128
#define KSTR  72
#define VSTR2 136
#define VS_OFF (KTILE * KSTR)
#define ATT_SMEM ((KTILE * KSTR + (KTILE / 2) * VSTR2) * 4)   // 71680 B

struct FlashCtx {
    const float* Ks;
    const float* Vp;
    int g, tg, k0, r0;
};

template <bool MASKED>
__device__ __forceinline__ void flash_jp_step(const FlashCtx& cx, int jp,
                                              const uint32_t qa[8][4],
                                              float o[8][4], float& l0, float& l1)
{
    const int g = cx.g, tg = cx.tg;
    const int j0 = 2 * jp, j1 = 2 * jp + 1;
    const float SCALE2 = 0.031882306f;   // (1/sqrt(2048)) * log2(e)

    float s0a[4] = {0.f, 0.f, 0.f, 0.f};
    float s0b[4] = {0.f, 0.f, 0.f, 0.f};
    float s1a[4] = {0.f, 0.f, 0.f, 0.f};
    float s1b[4] = {0.f, 0.f, 0.f, 0.f};
#pragma unroll
    for (int s = 0; s < 8; s++) {
        uint2 bp0 = *(const uint2*)&cx.Ks[(j0 * 8 + g) * KSTR + s * 8 + 2 * tg];
        uint2 bp1 = *(const uint2*)&cx.Ks[(j1 * 8 + g) * KSTR + s * 8 + 2 * tg];
        if (s < 4) {
            mma_tf32(s0a, qa[s], bp0.x, bp0.y);
            mma_tf32(s1a, qa[s], bp1.x, bp1.y);
        } else {
            mma_tf32(s0b, qa[s], bp0.x, bp0.y);
            mma_tf32(s1b, qa[s], bp1.x, bp1.y);
        }
    }

    uint32_t pa0[4], pa1[4];
    {
        float p00 = ex2f((s0a[0] + s0b[0]) * SCALE2);
        float p01 = ex2f((s0a[1] + s0b[1]) * SCALE2);
        float p10 = ex2f((s0a[2] + s0b[2]) * SCALE2);
        float p11 = ex2f((s0a[3] + s0b[3]) * SCALE2);
        if (MASKED) {
            const int c0 = cx.k0 + j0 * 8 + 2 * tg;
            if (c0     > cx.r0)     p00 = 0.f;
            if (c0 + 1 > cx.r0)     p01 = 0.f;
            if (c0     > cx.r0 + 8) p10 = 0.f;
            if (c0 + 1 > cx.r0 + 8) p11 = 0.f;
        }
        l0 += p00 + p01; l1 += p10 + p11;
        pa0[0] = __float_as_uint(p00); pa0[1] = __float_as_uint(p10);
        pa0[2] = __float_as_uint(p01); pa0[3] = __float_as_uint(p11);
    }
    {
        float p00 = ex2f((s1a[0] + s1b[0]) * SCALE2);
        float p01 = ex2f((s1a[1] + s1b[1]) * SCALE2);
        float p10 = ex2f((s1a[2] + s1b[2]) * SCALE2);
        float p11 = ex2f((s1a[3] + s1b[3]) * SCALE2);
        if (MASKED) {
            const int c0 = cx.k0 + j1 * 8 + 2 * tg;
            if (c0     > cx.r0)     p00 = 0.f;
            if (c0 + 1 > cx.r0)     p01 = 0.f;
            if (c0     > cx.r0 + 8) p10 = 0.f;
            if (c0 + 1 > cx.r0 + 8) p11 = 0.f;
        }
        l0 += p00 + p01; l1 += p10 + p11;
        pa1[0] = __float_as_uint(p00); pa1[1] = __float_as_uint(p10);
        pa1[2] = __float_as_uint(p01); pa1[3] = __float_as_uint(p11);
    }

#pragma unroll
    for (int j = 0; j < 8; j++) {
        const int col = j * 8 + g;
        uint2 v0 = *(const uint2*)&cx.Vp[(j0 * 4 + tg) * VSTR2 + 2 * col];
        mma_tf32(o[j], pa0, v0.x, v0.y);
        uint2 v1 = *(const uint2*)&cx.Vp[(j1 * 4 + tg) * VSTR2 + 2 * col];
        mma_tf32(o[j], pa1, v1.x, v1.y);
    }
}

__global__ __launch_bounds__(256, 2)
void flash_tf32(const float* __restrict__ gq, const float* __restrict__ gk,
                const float* __restrict__ gv, float* __restrict__ out)
{
    extern __shared__ float sm[];
    float* Ks = sm;
    float* Vp = sm + VS_OFF;

    const int x    = blockIdx.x;       // 0..7
    const int h    = blockIdx.y;
    const int b    = blockIdx.z;
    const int t    = threadIdx.x;
    const int w    = t >> 5;
    const int lane = t & 31;
    const int g    = lane >> 2;
    const int tg   = lane & 3;
    const int w16  = w * 16;

    FlashCtx cx;
    cx.Ks = Ks; cx.Vp = Vp; cx.g = g; cx.tg = tg;

#pragma unroll 1
    for (int half = 0; half < 2; half++) {
        const int qt = half ? (15 - x) : x;
        const int q0 = qt * 128;
        const int r0 = q0 + w16 + g;
        cx.r0 = r0;

        // Q fragments in registers for this tile (pre-rounded tf32)
        const float* qbase = gq + (size_t)(b * SEQ) * DMODEL + h * HDIM;
        uint32_t qa[8][4];
#pragma unroll
        for (int s = 0; s < 8; s++) {
            qa[s][0] = __float_as_uint(qbase[(size_t)r0 * DMODEL + s * 8 + tg]);
            qa[s][1] = __float_as_uint(qbase[(size_t)(r0 + 8) * DMODEL + s * 8 + tg]);
            qa[s][2] = __float_as_uint(qbase[(size_t)r0 * DMODEL + s * 8 + tg + 4]);
            qa[s][3] = __float_as_uint(qbase[(size_t)(r0 + 8) * DMODEL + s * 8 + tg + 4]);
        }

        float o[8][4];
#pragma unroll
        for (int j = 0; j < 8; j++)
#pragma unroll
            for (int i = 0; i < 4; i++) o[j][i] = 0.f;
        float l0 = 0.f, l1 = 0.f;

        const int nkt = qt + 1;
        for (int kt = 0; kt < nkt; kt++) {
            const int k0 = kt * KTILE;
            cx.k0 = k0;
            __syncthreads();    // previous tile's smem fully consumed

            // --- K tile: pair-permuted (d, d+4 interleaved) ---
            {
                const float* kb = gk + (size_t)(b * SEQ + k0) * HDIM;
#pragma unroll
                for (int i = 0; i < 4; i++) {
                    int task = t + i * 256;
                    int key = task >> 3, sg = task & 7;
                    const float* src = kb + (size_t)key * HDIM + sg * 8;
                    float4 u0 = *(const float4*)src;
                    float4 u1 = *(const float4*)(src + 4);
                    float* dst = Ks + key * KSTR + sg * 8;
                    *(float4*)dst       = make_float4(u0.x, u1.x, u0.y, u1.y);
                    *(float4*)(dst + 4) = make_float4(u0.z, u1.z, u0.w, u1.w);
                }
            }
            // --- V tile: row-pair interleaved, float4 in/out ---
            {
                const float* vb = gv + (size_t)(b * SEQ + k0) * DMODEL + h * HDIM;
#pragma unroll
                for (int i = 0; i < 4; i++) {
                    int task = t + i * 256;
                    int pr = task >> 4, cq = task & 15;
                    const float* src = vb + (size_t)(2 * pr) * DMODEL + 4 * cq;
                    float4 v0 = *(const float4*)src;
                    float4 v1 = *(const float4*)(src + DMODEL);
                    float* dst = Vp + pr * VSTR2 + 8 * cq;
                    *(float4*)dst       = make_float4(v0.x, v1.x, v0.y, v1.y);
                    *(float4*)(dst + 4) = make_float4(v0.z, v1.z, v0.w, v1.w);
                }
            }
            __syncthreads();

            if (kt < qt) {
#pragma unroll
                for (int jp = 0; jp < 8; jp++)
                    flash_jp_step<false>(cx, jp, qa, o, l0, l1);
            } else {
                // causal tile: warp w only needs jp <= w
                for (int jp = 0; jp <= w; jp++)
                    flash_jp_step<true>(cx, jp, qa, o, l0, l1);
            }
        }

        // row sums across the 4-thread group, then normalize + store
        l0 += __shfl_xor_sync(0xffffffffu, l0, 1);
        l0 += __shfl_xor_sync(0xffffffffu, l0, 2);
        l1 += __shfl_xor_sync(0xffffffffu, l1, 1);
        l1 += __shfl_xor_sync(0xffffffffu, l1, 2);
        const float inv0 = 1.f / l0;
        const float inv1 = 1.f / l1;

        float* ob = out + (size_t)(b * SEQ) * DMODEL + h * HDIM;
#pragma unroll
        for (int j = 0; j < 8; j++) {
            const int col = j * 8 + 2 * tg;
            float2 lo, hi;
            lo.x = o[j][0] * inv0;
            lo.y = o[j][1] * inv0;
            hi.x = o[j][2] * inv1;
            hi.y = o[j][3] * inv1;
            *(float2*)&ob[(size_t)r0 * DMODEL + col]       = lo;
            *(float2*)&ob[(size_t)(r0 + 8) * DMODEL + col] = hi;
        }
    }
}

// ---------------------------------------------------------------------------
extern "C" void kernel_launch(void* const* d_in, const int* in_sizes, int n_in,
                              void* d_out, int out_size)
{
    const float* x  = (const float*)d_in[0];
    const float* Wq = (const float*)d_in[1];
    const float* bq = (const float*)d_in[2];
    const float* Wk = (const float*)d_in[3];
    const float* Wv = (const float*)d_in[4];
    const float* bv = (const float*)d_in[5];
    float* out = (float*)d_out;

    float *qp, *kp, *vp;
    cudaGetSymbolAddress((void**)&qp, g_q);
    cudaGetSymbolAddress((void**)&kp, g_k);
    cudaGetSymbolAddress((void**)&vp, g_v);

    gemm_qkv<<<dim3(9, 64), 256>>>(x, Wq, bq, Wk, Wv, bv, qp, kp, vp);

    cudaFuncSetAttribute(flash_tf32, cudaFuncAttributeMaxDynamicSharedMemorySize, ATT_SMEM);
    flash_tf32<<<dim3(8, HEADS, BATCH), 256, ATT_SMEM>>>(qp, kp, vp, out);
}

// round 9
// speedup vs baseline: 1.0232x; 1.0232x over previous
#include <cuda_runtime.h>
#include <cstdint>
#include <math.h>

#define BATCH  4
#define SEQ    2048
#define DMODEL 512
#define HEADS  8
#define HDIM   64

// tf32-rounded fp32 scratch (allocation-free rule: __device__ globals)
__device__ float g_q[BATCH * SEQ * DMODEL];
__device__ float g_k[BATCH * SEQ * HDIM];
__device__ float g_v[BATCH * SEQ * DMODEL];

// ---------------------------------------------------------------------------
// helpers (baseline PTX only — plain sm_103 target)
// ---------------------------------------------------------------------------
__device__ __forceinline__ uint32_t f2tf(float f) {
    uint32_t u;
    asm("cvt.rna.tf32.f32 %0, %1;" : "=r"(u) : "f"(f));
    return u;
}
__device__ __forceinline__ float ex2f(float x) {
    float r;
    asm("ex2.approx.f32 %0, %1;" : "=f"(r) : "f"(x));
    return r;
}
__device__ __forceinline__ void mma_tf32(float c[4], const uint32_t a[4],
                                         uint32_t b0, uint32_t b1) {
    asm volatile(
        "mma.sync.aligned.m16n8k8.row.col.f32.tf32.tf32.f32 "
        "{%0,%1,%2,%3}, {%4,%5,%6,%7}, {%8,%9}, {%0,%1,%2,%3};"
        : "+f"(c[0]), "+f"(c[1]), "+f"(c[2]), "+f"(c[3])
        : "r"(a[0]), "r"(a[1]), "r"(a[2]), "r"(a[3]), "r"(b0), "r"(b1));
}

// ---------------------------------------------------------------------------
// Fused QKV GEMM (Round-6 proven version): 128-row CTA, BK=32, 256 thr,
// register-prefetch double buffered, warp tile 16 rows x full width.
// grid = (9, 64): bx 0-3 Q slabs, 4-7 V slabs, 8 K.
// ---------------------------------------------------------------------------
#define APAD 40
#define WSTR 264

template <int NJ>
__device__ __forceinline__ void gemm_tile(
    const float* __restrict__ A, const float* __restrict__ W,
    const float* __restrict__ bias, float* __restrict__ C,
    int N, int n0, uint32_t* As, uint32_t* Wp)
{
    const int t    = threadIdx.x;
    const int w    = t >> 5;
    const int lane = t & 31;
    const int g    = lane >> 2;
    const int tg   = lane & 3;
    const int m0   = blockIdx.y * 128;
    const int w16  = w * 16;

    const int arow = t >> 2, asg = t & 3;
    constexpr int WIT = NJ / 8;
    const int wcq = t & (2 * NJ - 1);

    float acc[NJ][4];
#pragma unroll
    for (int j = 0; j < NJ; j++)
#pragma unroll
        for (int i = 0; i < 4; i++) acc[j][i] = 0.f;

    float4 afr[2][2];
    float4 wfr[WIT][2];

    auto loadA = [&](int k0) {
#pragma unroll
        for (int i = 0; i < 2; i++) {
            const float* src = A + (size_t)(m0 + arow + 64 * i) * DMODEL + k0 + asg * 8;
            afr[i][0] = *(const float4*)src;
            afr[i][1] = *(const float4*)(src + 4);
        }
    };
    auto loadW = [&](int k0) {
#pragma unroll
        for (int i = 0; i < WIT; i++) {
            const int p  = (NJ == 16) ? ((t >> 5) + 8 * i) : (t >> 4);
            const int r0 = 8 * (p >> 2) + (p & 3);
            const float* src = W + (size_t)(k0 + r0) * N + n0 + 4 * wcq;
            wfr[i][0] = *(const float4*)src;
            wfr[i][1] = *(const float4*)(src + 4 * N);
        }
    };
    auto storeA = [&]() {
#pragma unroll
        for (int i = 0; i < 2; i++) {
            uint32_t* d = As + (arow + 64 * i) * APAD + asg * 8;
            float4 u0 = afr[i][0], u1 = afr[i][1];
            *(uint4*)d       = make_uint4(f2tf(u0.x), f2tf(u1.x), f2tf(u0.y), f2tf(u1.y));
            *(uint4*)(d + 4) = make_uint4(f2tf(u0.z), f2tf(u1.z), f2tf(u0.w), f2tf(u1.w));
        }
    };
    auto storeW = [&]() {
#pragma unroll
        for (int i = 0; i < WIT; i++) {
            const int p = (NJ == 16) ? ((t >> 5) + 8 * i) : (t >> 4);
            uint32_t* d = Wp + p * WSTR + 8 * wcq;
            float4 w0 = wfr[i][0], w1 = wfr[i][1];
            *(uint4*)d       = make_uint4(f2tf(w0.x), f2tf(w1.x), f2tf(w0.y), f2tf(w1.y));
            *(uint4*)(d + 4) = make_uint4(f2tf(w0.z), f2tf(w1.z), f2tf(w0.w), f2tf(w1.w));
        }
    };

    loadA(0);
    loadW(0);

    for (int k0 = 0; k0 < DMODEL; k0 += 32) {
        storeA();
        storeW();
        __syncthreads();
        if (k0 + 32 < DMODEL) {
            loadA(k0 + 32);
            loadW(k0 + 32);
        }
#pragma unroll
        for (int s = 0; s < 4; s++) {
            uint2 aLo = *(const uint2*)&As[(w16 + g)     * APAD + 8 * s + 2 * tg];
            uint2 aHi = *(const uint2*)&As[(w16 + g + 8) * APAD + 8 * s + 2 * tg];
            uint32_t a[4] = {aLo.x, aHi.x, aLo.y, aHi.y};
            const uint32_t* wrow = Wp + (s * 4 + tg) * WSTR;
#pragma unroll
            for (int j = 0; j < NJ; j++) {
                uint2 bp = *(const uint2*)&wrow[2 * (j * 8 + g)];
                mma_tf32(acc[j], a, bp.x, bp.y);
            }
        }
        __syncthreads();
    }

#pragma unroll
    for (int j = 0; j < NJ; j++) {
        const int col = n0 + j * 8 + 2 * tg;
        const float b0v = bias ? bias[col] : 0.f;
        const float b1v = bias ? bias[col + 1] : 0.f;
        const int r0 = m0 + w16 + g;
        float2 lo, hi;
        lo.x = __uint_as_float(f2tf(acc[j][0] + b0v));
        lo.y = __uint_as_float(f2tf(acc[j][1] + b1v));
        hi.x = __uint_as_float(f2tf(acc[j][2] + b0v));
        hi.y = __uint_as_float(f2tf(acc[j][3] + b1v));
        *(float2*)&C[(size_t)r0 * N + col]       = lo;
        *(float2*)&C[(size_t)(r0 + 8) * N + col] = hi;
    }
}

__global__ __launch_bounds__(256, 2)
void gemm_qkv(const float* __restrict__ A,
              const float* __restrict__ Wq, const float* __restrict__ bq,
              const float* __restrict__ Wk,
              const float* __restrict__ Wv, const float* __restrict__ bv,
              float* __restrict__ Cq, float* __restrict__ Ck, float* __restrict__ Cv)
{
    __shared__ uint32_t As[128 * APAD];
    __shared__ uint32_t Wp[16 * WSTR];

    const int bx = blockIdx.x;
    if (bx < 4)
        gemm_tile<16>(A, Wq, bq, Cq, DMODEL, bx * 128, As, Wp);
    else if (bx < 8)
        gemm_tile<16>(A, Wv, bv, Cv, DMODEL, (bx - 4) * 128, As, Wp);
    else
        gemm_tile<8>(A, Wk, nullptr, Ck, HDIM, 0, As, Wp);
}

// ---------------------------------------------------------------------------
// tf32 flash attention, KTILE=64 with register-staged tile prefetch:
// LDGs for tile kt+1 issue right after tile kt's STS barrier, retiring under
// tile kt's compute. CTA = (x,h,b) does q-tiles {x,15-x}: 36 uniform iters.
// K pair-permuted (d,d+4), V row-pair interleaved -> all B loads LDS.64.
// No online rescale (logits bounded). tf32 minimum precision for PV (bf16
// fails the 1e-3 gate — error does not average out).
// ---------------------------------------------------------------------------
#define KTILE 64
#define KSTR  72
#define VSTR2 136
#define VS_OFF (KTILE * KSTR)
#define ATT_SMEM ((KTILE * KSTR + (KTILE / 2) * VSTR2) * 4)   // 35840 B

struct FlashCtx {
    const float* Ks;
    const float* Vp;
    int g, tg, k0, r0;
};

template <bool MASKED>
__device__ __forceinline__ void flash_jp_step(const FlashCtx& cx, int jp,
                                              const uint32_t qa[8][4],
                                              float o[8][4], float& l0, float& l1)
{
    const int g = cx.g, tg = cx.tg;
    const int j0 = 2 * jp, j1 = 2 * jp + 1;
    const float SCALE2 = 0.031882306f;   // (1/sqrt(2048)) * log2(e)

    float s0[4] = {0.f, 0.f, 0.f, 0.f};
    float s1[4] = {0.f, 0.f, 0.f, 0.f};
#pragma unroll
    for (int s = 0; s < 8; s++) {
        uint2 bp0 = *(const uint2*)&cx.Ks[(j0 * 8 + g) * KSTR + s * 8 + 2 * tg];
        uint2 bp1 = *(const uint2*)&cx.Ks[(j1 * 8 + g) * KSTR + s * 8 + 2 * tg];
        mma_tf32(s0, qa[s], bp0.x, bp0.y);
        mma_tf32(s1, qa[s], bp1.x, bp1.y);
    }

    uint32_t pa0[4], pa1[4];
    {
        float p00 = ex2f(s0[0] * SCALE2);
        float p01 = ex2f(s0[1] * SCALE2);
        float p10 = ex2f(s0[2] * SCALE2);
        float p11 = ex2f(s0[3] * SCALE2);
        if (MASKED) {
            const int c0 = cx.k0 + j0 * 8 + 2 * tg;
            if (c0     > cx.r0)     p00 = 0.f;
            if (c0 + 1 > cx.r0)     p01 = 0.f;
            if (c0     > cx.r0 + 8) p10 = 0.f;
            if (c0 + 1 > cx.r0 + 8) p11 = 0.f;
        }
        l0 += p00 + p01; l1 += p10 + p11;
        pa0[0] = __float_as_uint(p00); pa0[1] = __float_as_uint(p10);
        pa0[2] = __float_as_uint(p01); pa0[3] = __float_as_uint(p11);
    }
    {
        float p00 = ex2f(s1[0] * SCALE2);
        float p01 = ex2f(s1[1] * SCALE2);
        float p10 = ex2f(s1[2] * SCALE2);
        float p11 = ex2f(s1[3] * SCALE2);
        if (MASKED) {
            const int c0 = cx.k0 + j1 * 8 + 2 * tg;
            if (c0     > cx.r0)     p00 = 0.f;
            if (c0 + 1 > cx.r0)     p01 = 0.f;
            if (c0     > cx.r0 + 8) p10 = 0.f;
            if (c0 + 1 > cx.r0 + 8) p11 = 0.f;
        }
        l0 += p00 + p01; l1 += p10 + p11;
        pa1[0] = __float_as_uint(p00); pa1[1] = __float_as_uint(p10);
        pa1[2] = __float_as_uint(p01); pa1[3] = __float_as_uint(p11);
    }

#pragma unroll
    for (int j = 0; j < 8; j++) {
        const int col = j * 8 + g;
        uint2 v0 = *(const uint2*)&cx.Vp[(j0 * 4 + tg) * VSTR2 + 2 * col];
        mma_tf32(o[j], pa0, v0.x, v0.y);
        uint2 v1 = *(const uint2*)&cx.Vp[(j1 * 4 + tg) * VSTR2 + 2 * col];
        mma_tf32(o[j], pa1, v1.x, v1.y);
    }
}

__global__ __launch_bounds__(256, 2)
void flash_tf32(const float* __restrict__ gq, const float* __restrict__ gk,
                const float* __restrict__ gv, float* __restrict__ out)
{
    extern __shared__ float sm[];
    float* Ks = sm;
    float* Vp = sm + VS_OFF;

    const int x    = blockIdx.x;       // 0..7
    const int h    = blockIdx.y;
    const int b    = blockIdx.z;
    const int t    = threadIdx.x;
    const int w    = t >> 5;
    const int lane = t & 31;
    const int g    = lane >> 2;
    const int tg   = lane & 3;
    const int w16  = w * 16;

    FlashCtx cx;
    cx.Ks = Ks; cx.Vp = Vp; cx.g = g; cx.tg = tg;

    // ---- register staging for tile prefetch (KTILE=64) ----
    float4 kst[4], vst[4];
    const int kkey = t >> 3, ksg = t & 7;     // K task (x2: +32 keys)
    const int vpr  = t >> 4, vcq = t & 15;    // V task (x2: +16 prs)

    auto ldKV = [&](int k0) {
        const float* kb = gk + (size_t)(b * SEQ + k0) * HDIM;
        {
            const float* src = kb + (size_t)kkey * HDIM + ksg * 8;
            kst[0] = *(const float4*)src;
            kst[1] = *(const float4*)(src + 4);
            src += 32 * HDIM;
            kst[2] = *(const float4*)src;
            kst[3] = *(const float4*)(src + 4);
        }
        const float* vb = gv + (size_t)(b * SEQ + k0) * DMODEL + h * HDIM;
        {
            const float* src = vb + (size_t)(2 * vpr) * DMODEL + 4 * vcq;
            vst[0] = *(const float4*)src;
            vst[1] = *(const float4*)(src + DMODEL);
            src += (size_t)32 * DMODEL;
            vst[2] = *(const float4*)src;
            vst[3] = *(const float4*)(src + DMODEL);
        }
    };
    auto stKV = [&]() {
#pragma unroll
        for (int i = 0; i < 2; i++) {
            float4 u0 = kst[2 * i], u1 = kst[2 * i + 1];
            float* dst = Ks + (kkey + 32 * i) * KSTR + ksg * 8;
            *(float4*)dst       = make_float4(u0.x, u1.x, u0.y, u1.y);
            *(float4*)(dst + 4) = make_float4(u0.z, u1.z, u0.w, u1.w);
        }
#pragma unroll
        for (int i = 0; i < 2; i++) {
            float4 v0 = vst[2 * i], v1 = vst[2 * i + 1];
            float* dst = Vp + (vpr + 16 * i) * VSTR2 + 8 * vcq;
            *(float4*)dst       = make_float4(v0.x, v1.x, v0.y, v1.y);
            *(float4*)(dst + 4) = make_float4(v0.z, v1.z, v0.w, v1.w);
        }
    };

    const int qts0 = x, qts1 = 15 - x;
    ldKV(0);   // stage tile (half 0, kt 0)

#pragma unroll 1
    for (int half = 0; half < 2; half++) {
        const int qt = half ? qts1 : qts0;
        const int q0 = qt * 128;
        const int r0 = q0 + w16 + g;
        cx.r0 = r0;

        // Q fragments in registers for this tile (pre-rounded tf32)
        const float* qbase = gq + (size_t)(b * SEQ) * DMODEL + h * HDIM;
        uint32_t qa[8][4];
#pragma unroll
        for (int s = 0; s < 8; s++) {
            qa[s][0] = __float_as_uint(qbase[(size_t)r0 * DMODEL + s * 8 + tg]);
            qa[s][1] = __float_as_uint(qbase[(size_t)(r0 + 8) * DMODEL + s * 8 + tg]);
            qa[s][2] = __float_as_uint(qbase[(size_t)r0 * DMODEL + s * 8 + tg + 4]);
            qa[s][3] = __float_as_uint(qbase[(size_t)(r0 + 8) * DMODEL + s * 8 + tg + 4]);
        }

        float o[8][4];
#pragma unroll
        for (int j = 0; j < 8; j++)
#pragma unroll
            for (int i = 0; i < 4; i++) o[j][i] = 0.f;
        float l0 = 0.f, l1 = 0.f;

        const int nkt = 2 * qt + 2;
#pragma unroll 1
        for (int kt = 0; kt < nkt; kt++) {
            cx.k0 = kt * KTILE;
            __syncthreads();    // smem free (prev compute done)
            stKV();
            __syncthreads();    // tile ready

            // prefetch next tile into staging regs (overlaps compute)
            {
                int nh = half, nk = kt + 1;
                if (nk == nkt) { nh++; nk = 0; }
                if (nh < 2) ldKV(nk * KTILE);
            }

            if (kt < 2 * qt) {
#pragma unroll
                for (int jp = 0; jp < 4; jp++)
                    flash_jp_step<false>(cx, jp, qa, o, l0, l1);
            } else if (kt == 2 * qt) {
                // diag tile A (keys q0..q0+63): warps 0-3 partial, 4-7 full
                if (w >= 4) {
#pragma unroll
                    for (int jp = 0; jp < 4; jp++)
                        flash_jp_step<false>(cx, jp, qa, o, l0, l1);
                } else {
                    for (int jp = 0; jp <= w; jp++)
                        flash_jp_step<true>(cx, jp, qa, o, l0, l1);
                }
            } else {
                // diag tile B (keys q0+64..q0+127): warps 0-3 fully masked
                if (w >= 4) {
                    for (int jp = 0; jp <= w - 4; jp++)
                        flash_jp_step<true>(cx, jp, qa, o, l0, l1);
                }
            }
        }

        // row sums across the 4-thread group, then normalize + store
        l0 += __shfl_xor_sync(0xffffffffu, l0, 1);
        l0 += __shfl_xor_sync(0xffffffffu, l0, 2);
        l1 += __shfl_xor_sync(0xffffffffu, l1, 1);
        l1 += __shfl_xor_sync(0xffffffffu, l1, 2);
        const float inv0 = 1.f / l0;
        const float inv1 = 1.f / l1;

        float* ob = out + (size_t)(b * SEQ) * DMODEL + h * HDIM;
#pragma unroll
        for (int j = 0; j < 8; j++) {
            const int col = j * 8 + 2 * tg;
            float2 lo, hi;
            lo.x = o[j][0] * inv0;
            lo.y = o[j][1] * inv0;
            hi.x = o[j][2] * inv1;
            hi.y = o[j][3] * inv1;
            *(float2*)&ob[(size_t)r0 * DMODEL + col]       = lo;
            *(float2*)&ob[(size_t)(r0 + 8) * DMODEL + col] = hi;
        }
    }
}

// ---------------------------------------------------------------------------
extern "C" void kernel_launch(void* const* d_in, const int* in_sizes, int n_in,
                              void* d_out, int out_size)
{
    const float* x  = (const float*)d_in[0];
    const float* Wq = (const float*)d_in[1];
    const float* bq = (const float*)d_in[2];
    const float* Wk = (const float*)d_in[3];
    const float* Wv = (const float*)d_in[4];
    const float* bv = (const float*)d_in[5];
    float* out = (float*)d_out;

    float *qp, *kp, *vp;
    cudaGetSymbolAddress((void**)&qp, g_q);
    cudaGetSymbolAddress((void**)&kp, g_k);
    cudaGetSymbolAddress((void**)&vp, g_v);

    gemm_qkv<<<dim3(9, 64), 256>>>(x, Wq, bq, Wk, Wv, bv, qp, kp, vp);

    cudaFuncSetAttribute(flash_tf32, cudaFuncAttributeMaxDynamicSharedMemorySize, ATT_SMEM);
    flash_tf32<<<dim3(8, HEADS, BATCH), 256, ATT_SMEM>>>(qp, kp, vp, out);
}